// round 3
// baseline (speedup 1.0000x reference)
#include <cuda_runtime.h>
#include <math.h>

#define BB      2
#define LL      2048
#define DMODEL  1024
#define DINNER  2048
#define DSTATE  16
#define DCONV   4
#define NROW    (BB * LL)           // 4096
#define NXDBL   (DINNER + 2*DSTATE) // 2080

// ---------------- scratch (static device globals; no allocation) ----------------
__device__ float g_xz  [(size_t)NROW * (2*DINNER)];  // 64 MB : [xs | z]
__device__ float g_u   [(size_t)NROW * DINNER];      // 32 MB
__device__ float g_xdbl[(size_t)NROW * NXDBL];       // 34 MB : [delta_in | B | C]
__device__ float g_dlt [(size_t)NROW * DINNER];      // 32 MB : softplus(delta)
__device__ float g_y   [(size_t)NROW * DINNER];      // 32 MB

// ---------------- helpers ----------------
__device__ __forceinline__ float softplus_f(float x) {
    return x > 20.f ? x : log1pf(__expf(x));
}
__device__ __forceinline__ float silu_f(float x) {
    return x / (1.f + __expf(-x));
}

// ---------------- SGEMM core: C[M,N] = A[M,K] @ B[K,N] (+ optional softplus/bias)
// 128x128 tile, BK=8, 256 threads, 8x8 per thread.
// Requires: M % 128 == 0, K % 8 == 0, N % 4 == 0 (N may be non-multiple of 128).
template<int EPI>  // 0 = plain, 1 = softplus(acc + bias[col])
__device__ __forceinline__
void sgemm_dev(const float* __restrict__ A, const float* __restrict__ B,
               const float* __restrict__ bias, float* __restrict__ C,
               int M, int N, int K, int lda, int ldb, int ldc)
{
    __shared__ float As[8][128];
    __shared__ float Bs[8][128];

    const int bm  = blockIdx.y * 128;
    const int bn  = blockIdx.x * 128;
    const int tid = threadIdx.x;
    const int tx  = tid & 15;        // 0..15 -> col group
    const int ty  = tid >> 4;        // 0..15 -> row group

    // A tile load mapping: 128 rows x 8 cols = 256 float4
    const int arow = tid >> 1;           // 0..127
    const int ac4  = (tid & 1) * 4;      // 0 or 4
    // B tile load mapping: 8 rows x 128 cols = 256 float4
    const int brow = tid >> 5;           // 0..7
    const int bc4  = (tid & 31) * 4;     // 0..124
    const bool bpred = (bn + bc4 + 3) < N;

    const float* Aptr = A + (size_t)(bm + arow) * lda + ac4;
    const float* Bptr = B + (size_t)brow * ldb + bn + bc4;

    float acc[8][8];
    #pragma unroll
    for (int i = 0; i < 8; ++i)
        #pragma unroll
        for (int j = 0; j < 8; ++j) acc[i][j] = 0.f;

    for (int k0 = 0; k0 < K; k0 += 8) {
        float4 av = *(const float4*)(Aptr + k0);
        As[ac4 + 0][arow] = av.x;
        As[ac4 + 1][arow] = av.y;
        As[ac4 + 2][arow] = av.z;
        As[ac4 + 3][arow] = av.w;

        float4 bv = bpred ? *(const float4*)(Bptr + (size_t)k0 * ldb)
                          : make_float4(0.f, 0.f, 0.f, 0.f);
        *(float4*)&Bs[brow][bc4] = bv;

        __syncthreads();

        #pragma unroll
        for (int k = 0; k < 8; ++k) {
            float ra[8], rb[8];
            *(float4*)(ra)     = *(const float4*)&As[k][ty * 8];
            *(float4*)(ra + 4) = *(const float4*)&As[k][ty * 8 + 4];
            *(float4*)(rb)     = *(const float4*)&Bs[k][tx * 8];
            *(float4*)(rb + 4) = *(const float4*)&Bs[k][tx * 8 + 4];
            #pragma unroll
            for (int i = 0; i < 8; ++i)
                #pragma unroll
                for (int j = 0; j < 8; ++j)
                    acc[i][j] = fmaf(ra[i], rb[j], acc[i][j]);
        }
        __syncthreads();
    }

    #pragma unroll
    for (int i = 0; i < 8; ++i) {
        const int row = bm + ty * 8 + i;
        #pragma unroll
        for (int j4 = 0; j4 < 8; j4 += 4) {
            const int col = bn + tx * 8 + j4;
            if (col + 3 < N) {
                float4 v;
                v.x = acc[i][j4 + 0];
                v.y = acc[i][j4 + 1];
                v.z = acc[i][j4 + 2];
                v.w = acc[i][j4 + 3];
                if (EPI == 1) {
                    v.x = softplus_f(v.x + bias[col + 0]);
                    v.y = softplus_f(v.y + bias[col + 1]);
                    v.z = softplus_f(v.z + bias[col + 2]);
                    v.w = softplus_f(v.w + bias[col + 3]);
                }
                *(float4*)(C + (size_t)row * ldc + col) = v;
            }
        }
    }
}

// ---- thin wrappers binding scratch globals at compile time (no cudaGetSymbolAddress) ----
__global__ __launch_bounds__(256)
void gemm_in(const float* __restrict__ x, const float* __restrict__ w_in) {
    // xz = x @ w_in : (4096 x 4096), K=1024
    sgemm_dev<0>(x, w_in, nullptr, g_xz, NROW, 2*DINNER, DMODEL, DMODEL, 2*DINNER, 2*DINNER);
}
__global__ __launch_bounds__(256)
void gemm_xdbl(const float* __restrict__ w_x) {
    // x_dbl = u @ w_x : (4096 x 2080), K=2048
    sgemm_dev<0>(g_u, w_x, nullptr, g_xdbl, NROW, NXDBL, DINNER, DINNER, NXDBL, NXDBL);
}
__global__ __launch_bounds__(256)
void gemm_dt(const float* __restrict__ w_dt, const float* __restrict__ b_dt) {
    // delta = softplus(x_dbl[:, :DINNER] @ w_dt + b_dt) : (4096 x 2048), K=2048
    sgemm_dev<1>(g_xdbl, w_dt, b_dt, g_dlt, NROW, DINNER, DINNER, NXDBL, DINNER, DINNER);
}
__global__ __launch_bounds__(256)
void gemm_out(const float* __restrict__ w_out, float* __restrict__ out) {
    // out = y @ w_out : (4096 x 1024), K=2048
    sgemm_dev<0>(g_y, w_out, nullptr, out, NROW, DMODEL, DINNER, DINNER, DMODEL, DMODEL);
}

// ---------------- causal depthwise conv1d + SiLU ----------------
// u[b,l,d] = silu( sum_k xs[b, l-3+k, d] * cw[d,0,k] + cb[d] ), xs = xz[:, :DINNER]
__global__ __launch_bounds__(256)
void conv_silu(const float* __restrict__ cw, const float* __restrict__ cb)
{
    const int idx = blockIdx.x * blockDim.x + threadIdx.x;   // < NROW*DINNER
    const int d   = idx & (DINNER - 1);
    const int row = idx >> 11;                               // b*LL + l
    const int l   = row & (LL - 1);

    float acc = cb[d];
    const float* base = g_xz + (size_t)row * (2 * DINNER) + d;
    #pragma unroll
    for (int k = 0; k < DCONV; ++k) {
        const int dl = k - (DCONV - 1);                      // -3..0
        if (l + dl >= 0)
            acc = fmaf(base[(long)dl * (2 * DINNER)], cw[d * DCONV + k], acc);
    }
    g_u[idx] = silu_f(acc);
}

// ---------------- selective scan (fused with +u*D and *silu(z) gate) ----------------
// 16 lanes per (b,d) channel, one state per lane; shfl_xor reduction over states.
// Grid: exactly BB*DINNER*DSTATE = 65536 threads (256 blocks x 256).
__global__ __launch_bounds__(256)
void scan_kernel(const float* __restrict__ A_log, const float* __restrict__ D_param)
{
    const int g  = blockIdx.x * blockDim.x + threadIdx.x;  // < BB*DINNER*DSTATE
    const int n  = g & (DSTATE - 1);
    const int ch = g >> 4;                                 // 0 .. BB*DINNER-1
    const int b  = ch >> 11;                               // ch / DINNER  (0..BB-1)
    const int d  = ch & (DINNER - 1);

    const float An = -__expf(A_log[d * DSTATE + n]);
    const float Dd = D_param[d];

    float h = 0.f;
    for (int l = 0; l < LL; ++l) {
        const int row = b * LL + l;
        const float dv = g_dlt[(size_t)row * DINNER + d];
        const float uv = g_u  [(size_t)row * DINNER + d];
        const float Bv = g_xdbl[(size_t)row * NXDBL + DINNER + n];
        const float Cv = g_xdbl[(size_t)row * NXDBL + DINNER + DSTATE + n];

        h = fmaf(__expf(dv * An), h, dv * Bv * uv);

        float p = h * Cv;
        p += __shfl_xor_sync(0xFFFFFFFFu, p, 8);
        p += __shfl_xor_sync(0xFFFFFFFFu, p, 4);
        p += __shfl_xor_sync(0xFFFFFFFFu, p, 2);
        p += __shfl_xor_sync(0xFFFFFFFFu, p, 1);

        if (n == 0) {
            const float zv = g_xz[(size_t)row * (2 * DINNER) + DINNER + d];
            g_y[(size_t)row * DINNER + d] = (p + uv * Dd) * silu_f(zv);
        }
    }
}

// ---------------- launch: kernel launches ONLY, no other runtime APIs ----------------
extern "C" void kernel_launch(void* const* d_in, const int* in_sizes, int n_in,
                              void* d_out, int out_size)
{
    const float* x      = (const float*)d_in[0];
    const float* w_in   = (const float*)d_in[1];
    const float* conv_w = (const float*)d_in[2];
    const float* conv_b = (const float*)d_in[3];
    const float* w_x    = (const float*)d_in[4];
    const float* w_dt   = (const float*)d_in[5];
    const float* b_dt   = (const float*)d_in[6];
    const float* A_log  = (const float*)d_in[7];
    const float* D_par  = (const float*)d_in[8];
    const float* w_out  = (const float*)d_in[9];
    float* out = (float*)d_out;

    const dim3 blk(256);

    // 1) xz = x @ w_in
    gemm_in<<<dim3((2*DINNER) / 128, NROW / 128), blk>>>(x, w_in);

    // 2) u = silu(causal_dwconv(xs) + conv_b)
    conv_silu<<<(NROW * DINNER) / 256, blk>>>(conv_w, conv_b);

    // 3) x_dbl = u @ w_x
    gemm_xdbl<<<dim3((NXDBL + 127) / 128, NROW / 128), blk>>>(w_x);

    // 4) delta = softplus(x_dbl[:, :DINNER] @ w_dt + b_dt)
    gemm_dt<<<dim3(DINNER / 128, NROW / 128), blk>>>(w_dt, b_dt);

    // 5) selective scan + u*D + silu(z) gate -> y   (exactly 65536 threads)
    scan_kernel<<<(BB * DINNER * DSTATE) / 256, blk>>>(A_log, D_par);

    // 6) out = y @ w_out
    gemm_out<<<dim3(DMODEL / 128, NROW / 128), blk>>>(w_out, out);
}

// round 4
// speedup vs baseline: 2.9122x; 2.9122x over previous
#include <cuda_runtime.h>
#include <math.h>
#include <stdint.h>

#define BB      2
#define LL      2048
#define DMODEL  1024
#define DINNER  2048
#define DSTATE  16
#define DCONV   4
#define NROW    (BB * LL)           // 4096
#define NXDBL   (DINNER + 2*DSTATE) // 2080

// ---------------- scratch (static device globals; no allocation) ----------------
__device__ float g_xz  [(size_t)NROW * (2*DINNER)];  // [xs | z]
__device__ float g_u   [(size_t)NROW * DINNER];
__device__ float g_xdbl[(size_t)NROW * NXDBL];       // [delta_in | B | C]
__device__ float g_dlt [(size_t)NROW * DINNER];
__device__ float g_y   [(size_t)NROW * DINNER];

// ---------------- helpers ----------------
__device__ __forceinline__ float softplus_f(float x) {
    return x > 20.f ? x : log1pf(__expf(x));
}
__device__ __forceinline__ float silu_f(float x) {
    return x / (1.f + __expf(-x));
}
__device__ __forceinline__ uint32_t f2tf32(float f) {
    uint32_t u;
    asm("cvt.rna.tf32.f32 %0, %1;" : "=r"(u) : "f"(f));
    return u;
}
__device__ __forceinline__ void mma_tf32(float* c,
    uint32_t a0, uint32_t a1, uint32_t a2, uint32_t a3,
    uint32_t b0, uint32_t b1)
{
    asm volatile(
        "mma.sync.aligned.m16n8k8.row.col.f32.tf32.tf32.f32 "
        "{%0,%1,%2,%3}, {%4,%5,%6,%7}, {%8,%9}, {%0,%1,%2,%3};"
        : "+f"(c[0]), "+f"(c[1]), "+f"(c[2]), "+f"(c[3])
        : "r"(a0), "r"(a1), "r"(a2), "r"(a3), "r"(b0), "r"(b1));
}

// ---------------- TF32 tensor-core GEMM ----------------
// C[M,N] = A[M,K] @ B[K,N], fp32 accumulate, tf32 inputs (cvt.rna at staging).
// Block tile 128x128, BK=16, 256 threads = 8 warps (2x4), warp tile 64x32.
// Smem (double buffered): A [128][20] u32, B [16][136] u32  -> 37.9 KB.
// Strides 20/136 make all mma fragment LDS patterns bank-conflict-free.
// Requires M%128==0, K%16==0, N%4==0 (N tiles predicated).
#define APAD 20
#define BPAD 136

template<int EPI>  // 0 = plain, 1 = softplus(acc + bias[col])
__device__ __forceinline__
void tgemm_dev(const float* __restrict__ A, const float* __restrict__ B,
               const float* __restrict__ bias, float* __restrict__ C,
               int M, int N, int K, int lda, int ldb, int ldc)
{
    __shared__ uint32_t As[2][128 * APAD];
    __shared__ uint32_t Bs[2][16 * BPAD];

    const int bm   = blockIdx.y * 128;
    const int bn   = blockIdx.x * 128;
    const int tid  = threadIdx.x;
    const int lane = tid & 31;
    const int w    = tid >> 5;
    const int wm   = (w & 1) * 64;       // warp row offset in tile
    const int wn   = (w >> 1) * 32;      // warp col offset in tile
    const int grp  = lane >> 2;          // 0..7
    const int t4   = lane & 3;           // 0..3

    // global->reg staging maps
    const int arow = tid >> 1;           // 0..127
    const int acol = (tid & 1) * 8;      // 0 or 8 (two float4 at acol, acol+4)
    const int brow = tid >> 4;           // 0..15
    const int bcol = (tid & 15) * 4;     // 0..60 (two float4 at bcol, bcol+64)

    const float* Aptr = A + (size_t)(bm + arow) * lda + acol;
    const float* Bbase = B + bn;
    const bool bp0 = (bn + bcol + 3) < N;
    const bool bp1 = (bn + bcol + 64 + 3) < N;

    float acc[4][4][4];
    #pragma unroll
    for (int i = 0; i < 4; ++i)
        #pragma unroll
        for (int j = 0; j < 4; ++j)
            #pragma unroll
            for (int r = 0; r < 4; ++r) acc[i][j][r] = 0.f;

    const int ntiles = K >> 4;
    float4 ra0, ra1, rb0, rb1;

    // ---- prologue: stage tile 0 ----
    {
        ra0 = *(const float4*)(Aptr + 0);
        ra1 = *(const float4*)(Aptr + 4);
        const float* bp = Bbase + (size_t)brow * ldb;
        rb0 = bp0 ? *(const float4*)(bp + bcol)      : make_float4(0,0,0,0);
        rb1 = bp1 ? *(const float4*)(bp + bcol + 64) : make_float4(0,0,0,0);

        uint32_t* as = &As[0][arow * APAD + acol];
        as[0] = f2tf32(ra0.x); as[1] = f2tf32(ra0.y); as[2] = f2tf32(ra0.z); as[3] = f2tf32(ra0.w);
        as[4] = f2tf32(ra1.x); as[5] = f2tf32(ra1.y); as[6] = f2tf32(ra1.z); as[7] = f2tf32(ra1.w);
        uint32_t* bs = &Bs[0][brow * BPAD + bcol];
        bs[0] = f2tf32(rb0.x); bs[1] = f2tf32(rb0.y); bs[2] = f2tf32(rb0.z); bs[3] = f2tf32(rb0.w);
        bs += 64;
        bs[0] = f2tf32(rb1.x); bs[1] = f2tf32(rb1.y); bs[2] = f2tf32(rb1.z); bs[3] = f2tf32(rb1.w);
    }
    __syncthreads();

    for (int t = 0; t < ntiles; ++t) {
        const int cur = t & 1;
        const bool more = (t + 1) < ntiles;

        // issue next tile's global loads early
        if (more) {
            const int k0 = (t + 1) << 4;
            ra0 = *(const float4*)(Aptr + k0);
            ra1 = *(const float4*)(Aptr + k0 + 4);
            const float* bp = Bbase + (size_t)(k0 + brow) * ldb;
            rb0 = bp0 ? *(const float4*)(bp + bcol)      : make_float4(0,0,0,0);
            rb1 = bp1 ? *(const float4*)(bp + bcol + 64) : make_float4(0,0,0,0);
        }

        // compute on current buffer: 2 k8 slices
        #pragma unroll
        for (int kk = 0; kk < 2; ++kk) {
            const int kb = kk * 8;
            uint32_t af[4][4];
            #pragma unroll
            for (int i = 0; i < 4; ++i) {
                const int r0 = wm + i * 16 + grp;
                af[i][0] = As[cur][ r0      * APAD + kb + t4];
                af[i][1] = As[cur][(r0 + 8) * APAD + kb + t4];
                af[i][2] = As[cur][ r0      * APAD + kb + t4 + 4];
                af[i][3] = As[cur][(r0 + 8) * APAD + kb + t4 + 4];
            }
            uint32_t bf[4][2];
            #pragma unroll
            for (int j = 0; j < 4; ++j) {
                const int c0 = wn + j * 8 + grp;
                bf[j][0] = Bs[cur][(kb + t4)     * BPAD + c0];
                bf[j][1] = Bs[cur][(kb + t4 + 4) * BPAD + c0];
            }
            #pragma unroll
            for (int i = 0; i < 4; ++i)
                #pragma unroll
                for (int j = 0; j < 4; ++j)
                    mma_tf32(acc[i][j], af[i][0], af[i][1], af[i][2], af[i][3],
                             bf[j][0], bf[j][1]);
        }

        if (more) {
            const int nxt = 1 - cur;
            uint32_t* as = &As[nxt][arow * APAD + acol];
            as[0] = f2tf32(ra0.x); as[1] = f2tf32(ra0.y); as[2] = f2tf32(ra0.z); as[3] = f2tf32(ra0.w);
            as[4] = f2tf32(ra1.x); as[5] = f2tf32(ra1.y); as[6] = f2tf32(ra1.z); as[7] = f2tf32(ra1.w);
            uint32_t* bs = &Bs[nxt][brow * BPAD + bcol];
            bs[0] = f2tf32(rb0.x); bs[1] = f2tf32(rb0.y); bs[2] = f2tf32(rb0.z); bs[3] = f2tf32(rb0.w);
            bs += 64;
            bs[0] = f2tf32(rb1.x); bs[1] = f2tf32(rb1.y); bs[2] = f2tf32(rb1.z); bs[3] = f2tf32(rb1.w);
            __syncthreads();
        }
    }

    // ---- epilogue ----
    #pragma unroll
    for (int i = 0; i < 4; ++i) {
        const int row = bm + wm + i * 16 + grp;
        #pragma unroll
        for (int j = 0; j < 4; ++j) {
            const int col = bn + wn + j * 8 + 2 * t4;
            if (col + 1 < N) {
                float c0 = acc[i][j][0], c1 = acc[i][j][1];
                float c2 = acc[i][j][2], c3 = acc[i][j][3];
                if (EPI == 1) {
                    const float bz0 = bias[col], bz1 = bias[col + 1];
                    c0 = softplus_f(c0 + bz0); c1 = softplus_f(c1 + bz1);
                    c2 = softplus_f(c2 + bz0); c3 = softplus_f(c3 + bz1);
                }
                *(float2*)(C + (size_t)row * ldc + col)       = make_float2(c0, c1);
                *(float2*)(C + (size_t)(row + 8) * ldc + col) = make_float2(c2, c3);
            }
        }
    }
}

// ---- thin wrappers binding scratch globals at compile time ----
__global__ __launch_bounds__(256)
void gemm_in(const float* __restrict__ x, const float* __restrict__ w_in) {
    tgemm_dev<0>(x, w_in, nullptr, g_xz, NROW, 2*DINNER, DMODEL, DMODEL, 2*DINNER, 2*DINNER);
}
__global__ __launch_bounds__(256)
void gemm_xdbl(const float* __restrict__ w_x) {
    tgemm_dev<0>(g_u, w_x, nullptr, g_xdbl, NROW, NXDBL, DINNER, DINNER, NXDBL, NXDBL);
}
__global__ __launch_bounds__(256)
void gemm_dt(const float* __restrict__ w_dt, const float* __restrict__ b_dt) {
    tgemm_dev<1>(g_xdbl, w_dt, b_dt, g_dlt, NROW, DINNER, DINNER, NXDBL, DINNER, DINNER);
}
__global__ __launch_bounds__(256)
void gemm_out(const float* __restrict__ w_out, float* __restrict__ out) {
    tgemm_dev<0>(g_y, w_out, nullptr, out, NROW, DMODEL, DINNER, DINNER, DMODEL, DMODEL);
}

// ---------------- causal depthwise conv1d + SiLU ----------------
__global__ __launch_bounds__(256)
void conv_silu(const float* __restrict__ cw, const float* __restrict__ cb)
{
    const int idx = blockIdx.x * blockDim.x + threadIdx.x;   // < NROW*DINNER
    const int d   = idx & (DINNER - 1);
    const int row = idx >> 11;                               // b*LL + l
    const int l   = row & (LL - 1);

    float acc = cb[d];
    const float* base = g_xz + (size_t)row * (2 * DINNER) + d;
    #pragma unroll
    for (int k = 0; k < DCONV; ++k) {
        const int dl = k - (DCONV - 1);                      // -3..0
        if (l + dl >= 0)
            acc = fmaf(base[(long)dl * (2 * DINNER)], cw[d * DCONV + k], acc);
    }
    g_u[idx] = silu_f(acc);
}

// ---------------- selective scan, unrolled + prefetched ----------------
// 16 lanes per (b,d) channel, one state per lane; shfl_xor reduction.
// Unroll L by 8: all 32+ loads of a super-iteration issue before the
// dependent h-chain -> memory latency overlapped, not serialized.
#define SU 8
__global__ __launch_bounds__(256)
void scan_kernel(const float* __restrict__ A_log, const float* __restrict__ D_param)
{
    const int g  = blockIdx.x * blockDim.x + threadIdx.x;  // < BB*DINNER*DSTATE
    const int n  = g & (DSTATE - 1);
    const int ch = g >> 4;
    const int b  = ch >> 11;
    const int d  = ch & (DINNER - 1);

    const float An = -__expf(A_log[d * DSTATE + n]);
    const float Dd = D_param[d];
    const bool lead = (n == 0);

    float h = 0.f;
    for (int l0 = 0; l0 < LL; l0 += SU) {
        float dv[SU], uv[SU], Bv[SU], Cv[SU], zv[SU];
        #pragma unroll
        for (int j = 0; j < SU; ++j) {
            const size_t row = (size_t)(b * LL + l0 + j);
            dv[j] = g_dlt [row * DINNER + d];
            uv[j] = g_u   [row * DINNER + d];
            Bv[j] = g_xdbl[row * NXDBL + DINNER + n];
            Cv[j] = g_xdbl[row * NXDBL + DINNER + DSTATE + n];
            zv[j] = lead ? g_xz[row * (2 * DINNER) + DINNER + d] : 0.f;
        }
        float e[SU], dbu[SU];
        #pragma unroll
        for (int j = 0; j < SU; ++j) {
            e[j]   = __expf(dv[j] * An);
            dbu[j] = dv[j] * Bv[j] * uv[j];
        }
        #pragma unroll
        for (int j = 0; j < SU; ++j) {
            h = fmaf(e[j], h, dbu[j]);
            float p = h * Cv[j];
            p += __shfl_xor_sync(0xFFFFFFFFu, p, 8);
            p += __shfl_xor_sync(0xFFFFFFFFu, p, 4);
            p += __shfl_xor_sync(0xFFFFFFFFu, p, 2);
            p += __shfl_xor_sync(0xFFFFFFFFu, p, 1);
            if (lead) {
                const size_t row = (size_t)(b * LL + l0 + j);
                g_y[row * DINNER + d] = (p + uv[j] * Dd) * silu_f(zv[j]);
            }
        }
    }
}

// ---------------- launch: kernel launches ONLY ----------------
extern "C" void kernel_launch(void* const* d_in, const int* in_sizes, int n_in,
                              void* d_out, int out_size)
{
    const float* x      = (const float*)d_in[0];
    const float* w_in   = (const float*)d_in[1];
    const float* conv_w = (const float*)d_in[2];
    const float* conv_b = (const float*)d_in[3];
    const float* w_x    = (const float*)d_in[4];
    const float* w_dt   = (const float*)d_in[5];
    const float* b_dt   = (const float*)d_in[6];
    const float* A_log  = (const float*)d_in[7];
    const float* D_par  = (const float*)d_in[8];
    const float* w_out  = (const float*)d_in[9];
    float* out = (float*)d_out;

    const dim3 blk(256);

    // 1) xz = x @ w_in              (4096 x 4096, K=1024)
    gemm_in<<<dim3((2*DINNER)/128, NROW/128), blk>>>(x, w_in);

    // 2) u = silu(causal_dwconv(xs) + conv_b)
    conv_silu<<<(NROW * DINNER) / 256, blk>>>(conv_w, conv_b);

    // 3) x_dbl = u @ w_x            (4096 x 2080, K=2048)
    gemm_xdbl<<<dim3((NXDBL + 127)/128, NROW/128), blk>>>(w_x);

    // 4) delta = softplus(x_dbl[:, :DINNER] @ w_dt + b_dt)  (4096 x 2048, K=2048)
    gemm_dt<<<dim3(DINNER/128, NROW/128), blk>>>(w_dt, b_dt);

    // 5) selective scan + u*D + silu(z) gate -> y   (65536 threads)
    scan_kernel<<<(BB * DINNER * DSTATE) / 256, blk>>>(A_log, D_par);

    // 6) out = y @ w_out            (4096 x 1024, K=2048)
    gemm_out<<<dim3(DMODEL/128, NROW/128), blk>>>(w_out, out);
}

// round 8
// speedup vs baseline: 3.0148x; 1.0352x over previous
#include <cuda_runtime.h>
#include <math.h>
#include <stdint.h>

#define BB      2
#define LL      2048
#define DMODEL  1024
#define DINNER  2048
#define DSTATE  16
#define DCONV   4
#define NROW    (BB * LL)           // 4096
#define NXDBL   (DINNER + 2*DSTATE) // 2080

// ---------------- scratch: SAME five-symbol structure as the passing R4 -----
__device__ float g_xz  [(size_t)NROW * (2*DINNER)];  // 64 MB : [xs | z]
__device__ float g_u   [(size_t)NROW * DINNER];      // 32 MB : rounded u
__device__ float g_xdbl[(size_t)NROW * NXDBL];       // 34 MB : [delta_in(rounded)|B|C]
__device__ float g_dlt [(size_t)DINNER * NROW];      // 32 MB : delta TRANSPOSED [d][row]
__device__ float g_y   [(size_t)NROW * DINNER];      // 32 MB : rounded y [row][d]

// ---------------- helpers ----------------
__device__ __forceinline__ float softplus_f(float x) {
    return x > 20.f ? x : log1pf(__expf(x));
}
__device__ __forceinline__ float silu_f(float x) {
    return x / (1.f + __expf(-x));
}
__device__ __forceinline__ uint32_t f2tf32(float f) {
    uint32_t u;
    asm("cvt.rna.tf32.f32 %0, %1;" : "=r"(u) : "f"(f));
    return u;
}
__device__ __forceinline__ float roundtf(float f) { return __uint_as_float(f2tf32(f)); }

__device__ __forceinline__ void mma_tf32(float* c,
    uint32_t a0, uint32_t a1, uint32_t a2, uint32_t a3,
    uint32_t b0, uint32_t b1)
{
    asm volatile(
        "mma.sync.aligned.m16n8k8.row.col.f32.tf32.tf32.f32 "
        "{%0,%1,%2,%3}, {%4,%5,%6,%7}, {%8,%9}, {%0,%1,%2,%3};"
        : "+f"(c[0]), "+f"(c[1]), "+f"(c[2]), "+f"(c[3])
        : "r"(a0), "r"(a1), "r"(a2), "r"(a3), "r"(b0), "r"(b1));
}

// ---------------- TF32 tensor-core GEMM (register-staged, as passing R4) ----
// Block tile 128x128, BK=16, 256 threads = 8 warps, warp tile 64x32.
// CVTA: 1 = cvt A on staging (raw fp32 A); 0 = A pre-rounded, store raw bits.
// EPI:  0 plain | 1 softplus(acc+bias) | 2 round cols<DINNER | 4 softplus+bias
//       then TRANSPOSED store C_t[col][row] (ldc = rows of C_t = NROW)
#define APAD 20
#define BPAD 136

template<int CVTA, int EPI>
__device__ __forceinline__
void tgemm_dev(const float* __restrict__ A, const float* __restrict__ B,
               const float* __restrict__ bias, float* __restrict__ C,
               int M, int N, int K, int lda, int ldb, int ldc)
{
    __shared__ uint32_t As[2][128 * APAD];
    __shared__ uint32_t Bs[2][16 * BPAD];

    const int bm   = blockIdx.y * 128;
    const int bn   = blockIdx.x * 128;
    const int tid  = threadIdx.x;
    const int lane = tid & 31;
    const int w    = tid >> 5;
    const int wm   = (w & 1) * 64;
    const int wn   = (w >> 1) * 32;
    const int grp  = lane >> 2;
    const int t4   = lane & 3;

    const int arow = tid >> 1;
    const int acol = (tid & 1) * 8;
    const int brow = tid >> 4;
    const int bcol = (tid & 15) * 4;
    const bool bp0 = (bn + bcol + 3) < N;
    const bool bp1 = (bn + bcol + 64 + 3) < N;

    const float* Aptr = A + (size_t)(bm + arow) * lda + acol;
    const float* Bb   = B + bn;

    float acc[4][4][4];
    #pragma unroll
    for (int i = 0; i < 4; ++i)
        #pragma unroll
        for (int j = 0; j < 4; ++j)
            #pragma unroll
            for (int r = 0; r < 4; ++r) acc[i][j][r] = 0.f;

    const int ntiles = K >> 4;
    float4 ra0, ra1, rb0, rb1;

    // ---- prologue: stage tile 0 ----
    {
        ra0 = *(const float4*)(Aptr + 0);
        ra1 = *(const float4*)(Aptr + 4);
        const float* bp = Bb + (size_t)brow * ldb;
        rb0 = bp0 ? *(const float4*)(bp + bcol)      : make_float4(0,0,0,0);
        rb1 = bp1 ? *(const float4*)(bp + bcol + 64) : make_float4(0,0,0,0);

        uint32_t* as = &As[0][arow * APAD + acol];
        if (CVTA) {
            as[0] = f2tf32(ra0.x); as[1] = f2tf32(ra0.y); as[2] = f2tf32(ra0.z); as[3] = f2tf32(ra0.w);
            as[4] = f2tf32(ra1.x); as[5] = f2tf32(ra1.y); as[6] = f2tf32(ra1.z); as[7] = f2tf32(ra1.w);
        } else {
            as[0] = __float_as_uint(ra0.x); as[1] = __float_as_uint(ra0.y);
            as[2] = __float_as_uint(ra0.z); as[3] = __float_as_uint(ra0.w);
            as[4] = __float_as_uint(ra1.x); as[5] = __float_as_uint(ra1.y);
            as[6] = __float_as_uint(ra1.z); as[7] = __float_as_uint(ra1.w);
        }
        uint32_t* bs = &Bs[0][brow * BPAD + bcol];
        bs[0] = f2tf32(rb0.x); bs[1] = f2tf32(rb0.y); bs[2] = f2tf32(rb0.z); bs[3] = f2tf32(rb0.w);
        bs += 64;
        bs[0] = f2tf32(rb1.x); bs[1] = f2tf32(rb1.y); bs[2] = f2tf32(rb1.z); bs[3] = f2tf32(rb1.w);
    }
    __syncthreads();

    for (int t = 0; t < ntiles; ++t) {
        const int cur  = t & 1;
        const bool more = (t + 1) < ntiles;

        if (more) {
            const int k0 = (t + 1) << 4;
            ra0 = *(const float4*)(Aptr + k0);
            ra1 = *(const float4*)(Aptr + k0 + 4);
            const float* bp = Bb + (size_t)(k0 + brow) * ldb;
            rb0 = bp0 ? *(const float4*)(bp + bcol)      : make_float4(0,0,0,0);
            rb1 = bp1 ? *(const float4*)(bp + bcol + 64) : make_float4(0,0,0,0);
        }

        #pragma unroll
        for (int kk = 0; kk < 2; ++kk) {
            const int kb = kk * 8;
            uint32_t af[4][4];
            #pragma unroll
            for (int i = 0; i < 4; ++i) {
                const int r0 = wm + i * 16 + grp;
                af[i][0] = As[cur][ r0      * APAD + kb + t4];
                af[i][1] = As[cur][(r0 + 8) * APAD + kb + t4];
                af[i][2] = As[cur][ r0      * APAD + kb + t4 + 4];
                af[i][3] = As[cur][(r0 + 8) * APAD + kb + t4 + 4];
            }
            uint32_t bf[4][2];
            #pragma unroll
            for (int j = 0; j < 4; ++j) {
                const int c0 = wn + j * 8 + grp;
                bf[j][0] = Bs[cur][(kb + t4)     * BPAD + c0];
                bf[j][1] = Bs[cur][(kb + t4 + 4) * BPAD + c0];
            }
            #pragma unroll
            for (int i = 0; i < 4; ++i)
                #pragma unroll
                for (int j = 0; j < 4; ++j)
                    mma_tf32(acc[i][j], af[i][0], af[i][1], af[i][2], af[i][3],
                             bf[j][0], bf[j][1]);
        }

        if (more) {
            const int nxt = 1 - cur;
            uint32_t* as = &As[nxt][arow * APAD + acol];
            if (CVTA) {
                as[0] = f2tf32(ra0.x); as[1] = f2tf32(ra0.y); as[2] = f2tf32(ra0.z); as[3] = f2tf32(ra0.w);
                as[4] = f2tf32(ra1.x); as[5] = f2tf32(ra1.y); as[6] = f2tf32(ra1.z); as[7] = f2tf32(ra1.w);
            } else {
                as[0] = __float_as_uint(ra0.x); as[1] = __float_as_uint(ra0.y);
                as[2] = __float_as_uint(ra0.z); as[3] = __float_as_uint(ra0.w);
                as[4] = __float_as_uint(ra1.x); as[5] = __float_as_uint(ra1.y);
                as[6] = __float_as_uint(ra1.z); as[7] = __float_as_uint(ra1.w);
            }
            uint32_t* bs = &Bs[nxt][brow * BPAD + bcol];
            bs[0] = f2tf32(rb0.x); bs[1] = f2tf32(rb0.y); bs[2] = f2tf32(rb0.z); bs[3] = f2tf32(rb0.w);
            bs += 64;
            bs[0] = f2tf32(rb1.x); bs[1] = f2tf32(rb1.y); bs[2] = f2tf32(rb1.z); bs[3] = f2tf32(rb1.w);
            __syncthreads();
        }
    }

    // ---- epilogue ----
    #pragma unroll
    for (int i = 0; i < 4; ++i) {
        const int row = bm + wm + i * 16 + grp;
        #pragma unroll
        for (int j = 0; j < 4; ++j) {
            const int col = bn + wn + j * 8 + 2 * t4;
            if (col + 1 < N) {
                float c0 = acc[i][j][0], c1 = acc[i][j][1];
                float c2 = acc[i][j][2], c3 = acc[i][j][3];
                if (EPI == 1 || EPI == 4) {
                    const float bz0 = bias[col], bz1 = bias[col + 1];
                    c0 = softplus_f(c0 + bz0); c1 = softplus_f(c1 + bz1);
                    c2 = softplus_f(c2 + bz0); c3 = softplus_f(c3 + bz1);
                } else if (EPI == 2) {
                    if (col < DINNER) {
                        c0 = roundtf(c0); c1 = roundtf(c1);
                        c2 = roundtf(c2); c3 = roundtf(c3);
                    }
                }
                if (EPI == 4) {   // transposed store: C_t[col][row], ldc = NROW
                    C[(size_t)col       * ldc + row]     = c0;
                    C[(size_t)(col + 1) * ldc + row]     = c1;
                    C[(size_t)col       * ldc + row + 8] = c2;
                    C[(size_t)(col + 1) * ldc + row + 8] = c3;
                } else {
                    *(float2*)(C + (size_t)row * ldc + col)       = make_float2(c0, c1);
                    *(float2*)(C + (size_t)(row + 8) * ldc + col) = make_float2(c2, c3);
                }
            }
        }
    }
}

// ---- GEMM wrappers (bind scratch globals at compile time) ----
__global__ __launch_bounds__(256)
void gemm_in(const float* __restrict__ x, const float* __restrict__ w_in) {
    // xz = x @ w_in : (4096 x 4096), K=1024. A raw -> CVTA=1.
    tgemm_dev<1, 0>(x, w_in, nullptr, g_xz, NROW, 2*DINNER, DMODEL,
                    DMODEL, 2*DINNER, 2*DINNER);
}
__global__ __launch_bounds__(256)
void gemm_xdbl(const float* __restrict__ w_x) {
    // x_dbl = u @ w_x : A = g_u (pre-rounded) -> CVTA=0; round delta cols.
    tgemm_dev<0, 2>(g_u, w_x, nullptr, g_xdbl, NROW, NXDBL, DINNER,
                    DINNER, NXDBL, NXDBL);
}
__global__ __launch_bounds__(256)
void gemm_dt(const float* __restrict__ w_dt, const float* __restrict__ b_dt) {
    // delta_t[d][row] = softplus(x_dbl[:, :2048] @ w_dt + b_dt)^T
    // A cols [0,2048) of xdbl are pre-rounded -> CVTA=0. EPI=4: transposed store.
    tgemm_dev<0, 4>(g_xdbl, w_dt, b_dt, g_dlt, NROW, DINNER, DINNER,
                    NXDBL, DINNER, NROW);
}
__global__ __launch_bounds__(256)
void gemm_out(const float* __restrict__ w_out, float* __restrict__ out) {
    // out = y @ w_out : A = g_y (pre-rounded) -> CVTA=0.
    tgemm_dev<0, 0>(g_y, w_out, nullptr, out, NROW, DMODEL, DINNER,
                    DINNER, DMODEL, DMODEL);
}

// ---------------- causal depthwise conv1d + SiLU -> rounded u ---------------
__global__ __launch_bounds__(256)
void conv_silu(const float* __restrict__ cw, const float* __restrict__ cb)
{
    const int idx = blockIdx.x * blockDim.x + threadIdx.x;   // < NROW*DINNER
    const int d   = idx & (DINNER - 1);
    const int row = idx >> 11;                               // b*LL + l
    const int l   = row & (LL - 1);

    float acc = cb[d];
    const float* base = g_xz + (size_t)row * (2 * DINNER) + d;
    #pragma unroll
    for (int k = 0; k < DCONV; ++k) {
        const int dl = k - (DCONV - 1);                      // -3..0
        if (l + dl >= 0)
            acc = fmaf(base[(long)dl * (2 * DINNER)], cw[d * DCONV + k], acc);
    }
    g_u[idx] = roundtf(silu_f(acc));
}

// ---------------- selective scan: delta transposed, rest as passing R4 ------
// 16 lanes per (b,d) channel, one state per lane; shfl_xor reduction.
#define SU 8
__global__ __launch_bounds__(256)
void scan_kernel(const float* __restrict__ A_log, const float* __restrict__ D_param)
{
    const int g  = blockIdx.x * blockDim.x + threadIdx.x;  // < BB*DINNER*16
    const int n  = g & (DSTATE - 1);
    const int ch = g >> 4;
    const int b  = ch >> 11;
    const int d  = ch & (DINNER - 1);

    const float An = -__expf(A_log[d * DSTATE + n]);
    const float Dd = D_param[d];
    const bool lead = (n == 0);

    const float4* dp = (const float4*)(g_dlt + (size_t)d * NROW + (size_t)b * LL);

    float h = 0.f;
    for (int l0 = 0; l0 < LL; l0 += SU) {
        const int i4 = l0 >> 2;
        float4 d0 = dp[i4], d1 = dp[i4 + 1];
        const float dv[SU] = {d0.x, d0.y, d0.z, d0.w, d1.x, d1.y, d1.z, d1.w};

        float uv[SU], Bv[SU], Cv[SU], zv[SU];
        #pragma unroll
        for (int j = 0; j < SU; ++j) {
            const size_t row = (size_t)(b * LL + l0 + j);
            uv[j] = g_u   [row * DINNER + d];
            Bv[j] = g_xdbl[row * NXDBL + DINNER + n];
            Cv[j] = g_xdbl[row * NXDBL + DINNER + DSTATE + n];
            zv[j] = lead ? g_xz[row * (2 * DINNER) + DINNER + d] : 0.f;
        }

        float e[SU], dbu[SU];
        #pragma unroll
        for (int j = 0; j < SU; ++j) {
            e[j]   = __expf(dv[j] * An);
            dbu[j] = dv[j] * Bv[j] * uv[j];
        }

        #pragma unroll
        for (int j = 0; j < SU; ++j) {
            h = fmaf(e[j], h, dbu[j]);
            float p = h * Cv[j];
            p += __shfl_xor_sync(0xFFFFFFFFu, p, 8);
            p += __shfl_xor_sync(0xFFFFFFFFu, p, 4);
            p += __shfl_xor_sync(0xFFFFFFFFu, p, 2);
            p += __shfl_xor_sync(0xFFFFFFFFu, p, 1);
            if (lead) {
                const size_t row = (size_t)(b * LL + l0 + j);
                g_y[row * DINNER + d] = roundtf((p + uv[j] * Dd) * silu_f(zv[j]));
            }
        }
    }
}

// ---------------- launch: kernel launches ONLY ----------------
extern "C" void kernel_launch(void* const* d_in, const int* in_sizes, int n_in,
                              void* d_out, int out_size)
{
    const float* x      = (const float*)d_in[0];
    const float* w_in   = (const float*)d_in[1];
    const float* conv_w = (const float*)d_in[2];
    const float* conv_b = (const float*)d_in[3];
    const float* w_x    = (const float*)d_in[4];
    const float* w_dt   = (const float*)d_in[5];
    const float* b_dt   = (const float*)d_in[6];
    const float* A_log  = (const float*)d_in[7];
    const float* D_par  = (const float*)d_in[8];
    const float* w_out  = (const float*)d_in[9];
    float* out = (float*)d_out;

    const dim3 blk(256);

    // 1) xz = x @ w_in              (4096 x 4096, K=1024)
    gemm_in<<<dim3((2*DINNER)/128, NROW/128), blk>>>(x, w_in);

    // 2) u = round(silu(causal_dwconv(xs) + conv_b))
    conv_silu<<<(NROW * DINNER) / 256, blk>>>(conv_w, conv_b);

    // 3) x_dbl = u @ w_x            (4096 x 2080, K=2048); delta cols rounded
    gemm_xdbl<<<dim3((NXDBL + 127)/128, NROW/128), blk>>>(w_x);

    // 4) delta_t = softplus(x_dbl[:,:2048] @ w_dt + b_dt)^T  (stored [d][row])
    gemm_dt<<<dim3(DINNER/128, NROW/128), blk>>>(w_dt, b_dt);

    // 5) selective scan + u*D + silu(z) gate -> y (rounded)   (65536 threads)
    scan_kernel<<<(BB * DINNER * DSTATE) / 256, blk>>>(A_log, D_par);

    // 6) out = y @ w_out            (4096 x 1024, K=2048)
    gemm_out<<<dim3(DMODEL/128, NROW/128), blk>>>(w_out, out);
}

// round 9
// speedup vs baseline: 3.7303x; 1.2373x over previous
#include <cuda_runtime.h>
#include <cuda_fp16.h>
#include <math.h>
#include <stdint.h>

#define BB      2
#define LL      2048
#define DMODEL  1024
#define DINNER  2048
#define DSTATE  16
#define DCONV   4
#define NROW    (BB * LL)           // 4096
#define NXDBL   (DINNER + 2*DSTATE) // 2080

// ---------------- scratch (146 MB total; same 5-symbol style as passing R8) -
__device__ float  g_xz  [(size_t)NROW * (2*DINNER)];  // 64 MB : [xs | z] fp32
__device__ __half g_u   [(size_t)NROW * DINNER];      // 16 MB : u fp16 [row][d]
__device__ float  g_xdbl[(size_t)NROW * NXDBL];       // 34 MB : [delta_in | B | C] fp32
__device__ __half g_dlt [(size_t)DINNER * NROW];      // 16 MB : delta fp16 TRANSPOSED [d][row]
__device__ __half g_y   [(size_t)NROW * DINNER];      // 16 MB : y fp16 [row][d]

// ---------------- helpers ----------------
__device__ __forceinline__ float softplus_f(float x) {
    return x > 20.f ? x : log1pf(__expf(x));
}
__device__ __forceinline__ float silu_f(float x) {
    return x / (1.f + __expf(-x));
}
__device__ __forceinline__ uint32_t pack_h2(float lo, float hi) {
    __half2 h = __floats2half2_rn(lo, hi);   // lo -> .x (low half)
    return *(uint32_t*)&h;
}
__device__ __forceinline__ void mma_f16(float* c,
    uint32_t a0, uint32_t a1, uint32_t a2, uint32_t a3,
    uint32_t b0, uint32_t b1)
{
    asm volatile(
        "mma.sync.aligned.m16n8k16.row.col.f32.f16.f16.f32 "
        "{%0,%1,%2,%3}, {%4,%5,%6,%7}, {%8,%9}, {%0,%1,%2,%3};"
        : "+f"(c[0]), "+f"(c[1]), "+f"(c[2]), "+f"(c[3])
        : "r"(a0), "r"(a1), "r"(a2), "r"(a3), "r"(b0), "r"(b1));
}

// ---------------- FP16 tensor-core GEMM (register-staged double buffer) -----
// Block tile 128x128, BK=16, 256 threads = 8 warps (2x4), warp tile 64x32.
// One m16n8k16 MMA per (i,j) per K-tile (vs two k8 before).
// Smem: As [128][12] u32 (=8 half2 + pad), Bs [8][136] u32. 20.5 KB doubled.
// HALFA: 1 = A is native __half [M][lda]; 0 = A fp32, cvt at staging.
// EPI: 0 plain f32 | 1 softplus+bias f32 | 4 softplus+bias -> TRANSPOSED half
#define AP 12
#define BP 136

template<int HALFA, int EPI>
__device__ __forceinline__
void tgemm16_dev(const void* Avoid, const float* __restrict__ B,
                 const float* __restrict__ bias, void* Cvoid,
                 int M, int N, int K, int lda, int ldb, int ldc)
{
    __shared__ uint32_t As[2][128 * AP];
    __shared__ uint32_t Bs[2][8 * BP];

    const int bm   = blockIdx.y * 128;
    const int bn   = blockIdx.x * 128;
    const int tid  = threadIdx.x;
    const int lane = tid & 31;
    const int w    = tid >> 5;
    const int wm   = (w & 1) * 64;
    const int wn   = (w >> 1) * 32;
    const int grp  = lane >> 2;          // 0..7
    const int t4   = lane & 3;           // 0..3

    // A staging map: 128 rows x 16 halves; thread = (row, half-sel)
    const int arow = tid >> 1;
    const int hsel = tid & 1;            // 0 -> halves 0..7, 1 -> 8..15
    // B staging map: 8 k-pairs x 128 cols; thread = (k2, col4)
    const int bk2  = tid >> 5;           // 0..7
    const int bcol = (lane) * 4;         // 0..124
    const bool bp  = (bn + bcol + 3) < N;

    const float*  Af = (const float*)Avoid;
    const __half* Ah = (const __half*)Avoid;
    const float*  Bb = B + bn;

    float acc[4][4][4];
    #pragma unroll
    for (int i = 0; i < 4; ++i)
        #pragma unroll
        for (int j = 0; j < 4; ++j)
            #pragma unroll
            for (int r = 0; r < 4; ++r) acc[i][j][r] = 0.f;

    const int ntiles = K >> 4;
    float4 ra0, ra1, rb0, rb1;
    uint4  rau;

    // ---- prologue: stage tile 0 ----
    {
        if (HALFA) {
            rau = *(const uint4*)(Ah + (size_t)(bm + arow) * lda + hsel * 8);
            uint32_t* as = &As[0][arow * AP + hsel * 4];
            as[0] = rau.x; as[1] = rau.y; as[2] = rau.z; as[3] = rau.w;
        } else {
            const float* ap = Af + (size_t)(bm + arow) * lda + hsel * 8;
            ra0 = *(const float4*)(ap);
            ra1 = *(const float4*)(ap + 4);
            uint32_t* as = &As[0][arow * AP + hsel * 4];
            as[0] = pack_h2(ra0.x, ra0.y); as[1] = pack_h2(ra0.z, ra0.w);
            as[2] = pack_h2(ra1.x, ra1.y); as[3] = pack_h2(ra1.z, ra1.w);
        }
        const float* bp0 = Bb + (size_t)(2 * bk2)     * ldb + bcol;
        const float* bp1 = Bb + (size_t)(2 * bk2 + 1) * ldb + bcol;
        rb0 = bp ? *(const float4*)bp0 : make_float4(0,0,0,0);
        rb1 = bp ? *(const float4*)bp1 : make_float4(0,0,0,0);
        uint4 bv;
        bv.x = pack_h2(rb0.x, rb1.x); bv.y = pack_h2(rb0.y, rb1.y);
        bv.z = pack_h2(rb0.z, rb1.z); bv.w = pack_h2(rb0.w, rb1.w);
        *(uint4*)&Bs[0][bk2 * BP + bcol] = bv;
    }
    __syncthreads();

    for (int t = 0; t < ntiles; ++t) {
        const int  cur  = t & 1;
        const bool more = (t + 1) < ntiles;

        if (more) {
            const int k0 = (t + 1) << 4;
            if (HALFA) {
                rau = *(const uint4*)(Ah + (size_t)(bm + arow) * lda + k0 + hsel * 8);
            } else {
                const float* ap = Af + (size_t)(bm + arow) * lda + k0 + hsel * 8;
                ra0 = *(const float4*)(ap);
                ra1 = *(const float4*)(ap + 4);
            }
            const float* bp0 = Bb + (size_t)(k0 + 2 * bk2)     * ldb + bcol;
            const float* bp1 = Bb + (size_t)(k0 + 2 * bk2 + 1) * ldb + bcol;
            rb0 = bp ? *(const float4*)bp0 : make_float4(0,0,0,0);
            rb1 = bp ? *(const float4*)bp1 : make_float4(0,0,0,0);
        }

        // ---- compute: one m16n8k16 per (i,j) ----
        uint32_t af[4][4];
        #pragma unroll
        for (int i = 0; i < 4; ++i) {
            const int r0 = wm + i * 16 + grp;
            af[i][0] = As[cur][ r0      * AP + t4];
            af[i][1] = As[cur][(r0 + 8) * AP + t4];
            af[i][2] = As[cur][ r0      * AP + t4 + 4];
            af[i][3] = As[cur][(r0 + 8) * AP + t4 + 4];
        }
        uint32_t bf[4][2];
        #pragma unroll
        for (int j = 0; j < 4; ++j) {
            const int c0 = wn + j * 8 + grp;
            bf[j][0] = Bs[cur][ t4      * BP + c0];
            bf[j][1] = Bs[cur][(t4 + 4) * BP + c0];
        }
        #pragma unroll
        for (int i = 0; i < 4; ++i)
            #pragma unroll
            for (int j = 0; j < 4; ++j)
                mma_f16(acc[i][j], af[i][0], af[i][1], af[i][2], af[i][3],
                        bf[j][0], bf[j][1]);

        if (more) {
            const int nxt = 1 - cur;
            uint32_t* as = &As[nxt][arow * AP + hsel * 4];
            if (HALFA) {
                as[0] = rau.x; as[1] = rau.y; as[2] = rau.z; as[3] = rau.w;
            } else {
                as[0] = pack_h2(ra0.x, ra0.y); as[1] = pack_h2(ra0.z, ra0.w);
                as[2] = pack_h2(ra1.x, ra1.y); as[3] = pack_h2(ra1.z, ra1.w);
            }
            uint4 bv;
            bv.x = pack_h2(rb0.x, rb1.x); bv.y = pack_h2(rb0.y, rb1.y);
            bv.z = pack_h2(rb0.z, rb1.z); bv.w = pack_h2(rb0.w, rb1.w);
            *(uint4*)&Bs[nxt][bk2 * BP + bcol] = bv;
            __syncthreads();
        }
    }

    // ---- epilogue ----
    float*  Cf = (float*)Cvoid;
    __half* Ch = (__half*)Cvoid;
    #pragma unroll
    for (int i = 0; i < 4; ++i) {
        const int row = bm + wm + i * 16 + grp;
        #pragma unroll
        for (int j = 0; j < 4; ++j) {
            const int col = bn + wn + j * 8 + 2 * t4;
            if (col + 1 < N) {
                float c0 = acc[i][j][0], c1 = acc[i][j][1];
                float c2 = acc[i][j][2], c3 = acc[i][j][3];
                if (EPI == 1 || EPI == 4) {
                    const float bz0 = bias[col], bz1 = bias[col + 1];
                    c0 = softplus_f(c0 + bz0); c1 = softplus_f(c1 + bz1);
                    c2 = softplus_f(c2 + bz0); c3 = softplus_f(c3 + bz1);
                }
                if (EPI == 4) {   // transposed half store: C_t[col][row], ldc=NROW
                    Ch[(size_t)col       * ldc + row]     = __float2half_rn(c0);
                    Ch[(size_t)(col + 1) * ldc + row]     = __float2half_rn(c1);
                    Ch[(size_t)col       * ldc + row + 8] = __float2half_rn(c2);
                    Ch[(size_t)(col + 1) * ldc + row + 8] = __float2half_rn(c3);
                } else {
                    *(float2*)(Cf + (size_t)row * ldc + col)       = make_float2(c0, c1);
                    *(float2*)(Cf + (size_t)(row + 8) * ldc + col) = make_float2(c2, c3);
                }
            }
        }
    }
}

// ---- GEMM wrappers ----
__global__ __launch_bounds__(256)
void gemm_in(const float* __restrict__ x, const float* __restrict__ w_in) {
    // xz = x @ w_in : (4096 x 4096), K=1024. A fp32 -> cvt staging.
    tgemm16_dev<0, 0>(x, w_in, nullptr, g_xz, NROW, 2*DINNER, DMODEL,
                      DMODEL, 2*DINNER, 2*DINNER);
}
__global__ __launch_bounds__(256)
void gemm_xdbl(const float* __restrict__ w_x) {
    // x_dbl = u @ w_x : A native half.
    tgemm16_dev<1, 0>(g_u, w_x, nullptr, g_xdbl, NROW, NXDBL, DINNER,
                      DINNER, NXDBL, NXDBL);
}
__global__ __launch_bounds__(256)
void gemm_dt(const float* __restrict__ w_dt, const float* __restrict__ b_dt) {
    // delta_t[d][row] = softplus(x_dbl[:, :2048] @ w_dt + b_dt)^T  as half.
    tgemm16_dev<0, 4>(g_xdbl, w_dt, b_dt, g_dlt, NROW, DINNER, DINNER,
                      NXDBL, DINNER, NROW);
}
__global__ __launch_bounds__(256)
void gemm_out(const float* __restrict__ w_out, float* __restrict__ out) {
    // out = y @ w_out : A native half.
    tgemm16_dev<1, 0>(g_y, w_out, nullptr, out, NROW, DMODEL, DINNER,
                      DINNER, DMODEL, DMODEL);
}

// ---------------- causal depthwise conv1d + SiLU -> half u ------------------
__global__ __launch_bounds__(256)
void conv_silu(const float* __restrict__ cw, const float* __restrict__ cb)
{
    const int idx = blockIdx.x * blockDim.x + threadIdx.x;   // < NROW*DINNER
    const int d   = idx & (DINNER - 1);
    const int row = idx >> 11;                               // b*LL + l
    const int l   = row & (LL - 1);

    float acc = cb[d];
    const float* base = g_xz + (size_t)row * (2 * DINNER) + d;
    #pragma unroll
    for (int k = 0; k < DCONV; ++k) {
        const int dl = k - (DCONV - 1);                      // -3..0
        if (l + dl >= 0)
            acc = fmaf(base[(long)dl * (2 * DINNER)], cw[d * DCONV + k], acc);
    }
    g_u[idx] = __float2half_rn(silu_f(acc));
}

// ---------------- selective scan (delta/u/y fp16, B/C/z fp32) ---------------
// 16 lanes per (b,d) channel, one state per lane; shfl_xor reduction.
#define SU 8
__global__ __launch_bounds__(256)
void scan_kernel(const float* __restrict__ A_log, const float* __restrict__ D_param)
{
    const int g  = blockIdx.x * blockDim.x + threadIdx.x;  // < BB*DINNER*16
    const int n  = g & (DSTATE - 1);
    const int ch = g >> 4;
    const int b  = ch >> 11;
    const int d  = ch & (DINNER - 1);

    const float An = -__expf(A_log[d * DSTATE + n]);
    const float Dd = D_param[d];
    const bool lead = (n == 0);

    const uint4* dp = (const uint4*)(g_dlt + (size_t)d * NROW + (size_t)b * LL);

    float h = 0.f;
    for (int l0 = 0; l0 < LL; l0 += SU) {
        // 8 halves of delta in one 16B load (address uniform across the group)
        uint4 dr = dp[l0 >> 3];
        float2 dv01 = __half22float2(*(__half2*)&dr.x);
        float2 dv23 = __half22float2(*(__half2*)&dr.y);
        float2 dv45 = __half22float2(*(__half2*)&dr.z);
        float2 dv67 = __half22float2(*(__half2*)&dr.w);
        const float dv[SU] = {dv01.x, dv01.y, dv23.x, dv23.y,
                              dv45.x, dv45.y, dv67.x, dv67.y};

        float uv[SU], Bv[SU], Cv[SU], zv[SU];
        #pragma unroll
        for (int j = 0; j < SU; ++j) {
            const size_t row = (size_t)(b * LL + l0 + j);
            uv[j] = __half2float(g_u[row * DINNER + d]);
            Bv[j] = g_xdbl[row * NXDBL + DINNER + n];
            Cv[j] = g_xdbl[row * NXDBL + DINNER + DSTATE + n];
            zv[j] = lead ? g_xz[row * (2 * DINNER) + DINNER + d] : 0.f;
        }

        float e[SU], dbu[SU];
        #pragma unroll
        for (int j = 0; j < SU; ++j) {
            e[j]   = __expf(dv[j] * An);
            dbu[j] = dv[j] * Bv[j] * uv[j];
        }

        #pragma unroll
        for (int j = 0; j < SU; ++j) {
            h = fmaf(e[j], h, dbu[j]);
            float p = h * Cv[j];
            p += __shfl_xor_sync(0xFFFFFFFFu, p, 8);
            p += __shfl_xor_sync(0xFFFFFFFFu, p, 4);
            p += __shfl_xor_sync(0xFFFFFFFFu, p, 2);
            p += __shfl_xor_sync(0xFFFFFFFFu, p, 1);
            if (lead) {
                const size_t row = (size_t)(b * LL + l0 + j);
                g_y[row * DINNER + d] =
                    __float2half_rn((p + uv[j] * Dd) * silu_f(zv[j]));
            }
        }
    }
}

// ---------------- launch: kernel launches ONLY ----------------
extern "C" void kernel_launch(void* const* d_in, const int* in_sizes, int n_in,
                              void* d_out, int out_size)
{
    const float* x      = (const float*)d_in[0];
    const float* w_in   = (const float*)d_in[1];
    const float* conv_w = (const float*)d_in[2];
    const float* conv_b = (const float*)d_in[3];
    const float* w_x    = (const float*)d_in[4];
    const float* w_dt   = (const float*)d_in[5];
    const float* b_dt   = (const float*)d_in[6];
    const float* A_log  = (const float*)d_in[7];
    const float* D_par  = (const float*)d_in[8];
    const float* w_out  = (const float*)d_in[9];
    float* out = (float*)d_out;

    const dim3 blk(256);

    // 1) xz = x @ w_in              (4096 x 4096, K=1024)
    gemm_in<<<dim3((2*DINNER)/128, NROW/128), blk>>>(x, w_in);

    // 2) u = half(silu(causal_dwconv(xs) + conv_b))
    conv_silu<<<(NROW * DINNER) / 256, blk>>>(conv_w, conv_b);

    // 3) x_dbl = u @ w_x            (4096 x 2080, K=2048)
    gemm_xdbl<<<dim3((NXDBL + 127)/128, NROW/128), blk>>>(w_x);

    // 4) delta_t = softplus(x_dbl[:,:2048] @ w_dt + b_dt)^T  as half [d][row]
    gemm_dt<<<dim3(DINNER/128, NROW/128), blk>>>(w_dt, b_dt);

    // 5) selective scan + u*D + silu(z) gate -> y (half)   (65536 threads)
    scan_kernel<<<(BB * DINNER * DSTATE) / 256, blk>>>(A_log, D_par);

    // 6) out = y @ w_out            (4096 x 1024, K=2048)
    gemm_out<<<dim3(DMODEL/128, NROW/128), blk>>>(w_out, out);
}